// round 9
// baseline (speedup 1.0000x reference)
#include <cuda_runtime.h>
#include <math_constants.h>

#define BB 4
#define TE 1024
#define TD 512
#define HH 128
#define DTILE 7         // d's per CTA: 7, each owned by a 2-warp t-split pair
#define NPAIR 7
#define NW 14           // warps per CTA
#define NTILES 74       // ceil(512/7); 4*74 = 296 CTAs = 2 per SM
#define TCHUNK 32
#define HCHUNK 16       // chunks per warp-half
#define NTHREADS (NW * 32)          // 448
#define ROWPAD 33                   // float4s per padded smem row

// smem byte layout (static, ~39.7 KB; 2 CTAs/SM = 79.4 KB < 228 KB)
#define WSA_OFF 0
#define WSB_OFF 16896
#define UH_OFF  33792
#define V_OFF   37376
#define P_OFF   37888
#define SMEM_BYTES 39680

// Scratch (statically allocated; no cudaMalloc allowed anywhere)
__device__ float g_Ws[BB * TE * HH];   // enc @ W_a
__device__ float g_Uh[BB * TD * HH];   // dec @ U_a

__device__ __forceinline__ float tanh_fast(float x) {
    float y;
    asm("tanh.approx.f32 %0, %1;" : "=f"(y) : "f"(x));
    return y;
}

// ---------------------------------------------------------------------------
// Stage 1 (fused): rows 0..4095 -> g_Ws = enc @ W_a; rows 4096..6143 -> g_Uh.
// 4 rows per warp; a-loads vectorized (float4 per 4 h).
// ---------------------------------------------------------------------------
__global__ __launch_bounds__(256) void proj_all_kernel(
    const float* __restrict__ enc, const float* __restrict__ dec,
    const float* __restrict__ Wa,  const float* __restrict__ Ua)
{
    const int w    = threadIdx.x >> 5;
    const int lane = threadIdx.x & 31;
    const int gw   = blockIdx.x * 8 + w;      // 0..1535
    int r0 = gw * 4;

    const float* in; const float* W; float* out;
    if (r0 < BB * TE) { in = enc; W = Wa; out = g_Ws; }
    else              { r0 -= BB * TE; in = dec; W = Ua; out = g_Uh; }

    const float4* in4 = (const float4*)in;
    const float4* W4  = (const float4*)W;

    float4 acc0 = make_float4(0.f,0.f,0.f,0.f);
    float4 acc1 = acc0, acc2 = acc0, acc3 = acc0;

    #pragma unroll 4
    for (int hg = 0; hg < HH / 4; ++hg) {     // group of 4 h's
        float4 a0 = in4[(r0 + 0) * 32 + hg];  // warp-uniform .128 loads
        float4 a1 = in4[(r0 + 1) * 32 + hg];
        float4 a2 = in4[(r0 + 2) * 32 + hg];
        float4 a3 = in4[(r0 + 3) * 32 + hg];
        #pragma unroll
        for (int j = 0; j < 4; ++j) {
            float4 wv = W4[(hg * 4 + j) * 32 + lane];
            float s0 = (j == 0) ? a0.x : (j == 1) ? a0.y : (j == 2) ? a0.z : a0.w;
            float s1 = (j == 0) ? a1.x : (j == 1) ? a1.y : (j == 2) ? a1.z : a1.w;
            float s2 = (j == 0) ? a2.x : (j == 1) ? a2.y : (j == 2) ? a2.z : a2.w;
            float s3 = (j == 0) ? a3.x : (j == 1) ? a3.y : (j == 2) ? a3.z : a3.w;
            acc0.x = fmaf(s0, wv.x, acc0.x); acc0.y = fmaf(s0, wv.y, acc0.y);
            acc0.z = fmaf(s0, wv.z, acc0.z); acc0.w = fmaf(s0, wv.w, acc0.w);
            acc1.x = fmaf(s1, wv.x, acc1.x); acc1.y = fmaf(s1, wv.y, acc1.y);
            acc1.z = fmaf(s1, wv.z, acc1.z); acc1.w = fmaf(s1, wv.w, acc1.w);
            acc2.x = fmaf(s2, wv.x, acc2.x); acc2.y = fmaf(s2, wv.y, acc2.y);
            acc2.z = fmaf(s2, wv.z, acc2.z); acc2.w = fmaf(s2, wv.w, acc2.w);
            acc3.x = fmaf(s3, wv.x, acc3.x); acc3.y = fmaf(s3, wv.y, acc3.y);
            acc3.z = fmaf(s3, wv.z, acc3.z); acc3.w = fmaf(s3, wv.w, acc3.w);
        }
    }
    ((float4*)out)[(r0 + 0) * 32 + lane] = acc0;
    ((float4*)out)[(r0 + 1) * 32 + lane] = acc1;
    ((float4*)out)[(r0 + 2) * 32 + lane] = acc2;
    ((float4*)out)[(r0 + 3) * 32 + lane] = acc3;
}

// ---------------------------------------------------------------------------
// Stage 2: fused energies + online softmax + context.
// 14 warps; warps j and j+7 own d = tile*7 + j: warp j covers chunks 0..15
// (buffer A), warp j+7 covers chunks 16..31 (buffer B). Flash-style partials
// merged across the warp pair at the end. 296 CTAs -> 2 CTAs per SM.
// ---------------------------------------------------------------------------
__global__ __launch_bounds__(NTHREADS, 2) void attn_main_kernel(
    const float* __restrict__ enc,   // [B, TE, H]
    const float* __restrict__ Va,    // [H]
    float* __restrict__ c_out,       // [B, TD, H]
    float* __restrict__ e_out)       // [B, TD, TE]
{
    __shared__ __align__(16) char sm[SMEM_BYTES];
    float4* wsA  = (float4*)(sm + WSA_OFF);   // 32 rows x ROWPAD
    float4* wsB  = (float4*)(sm + WSB_OFF);
    float4* uh_s = (float4*)(sm + UH_OFF);    // 7 rows x 32
    float4* v_s  = (float4*)(sm + V_OFF);
    float*  p_s  = (float*) (sm + P_OFF);     // [14][32]

    const int tid  = threadIdx.x;
    const int w    = tid >> 5;
    const int lane = tid & 31;
    const int half = (w >= NPAIR);
    const int j    = half ? w - NPAIR : w;    // pair index 0..6
    const int b    = blockIdx.y;
    const int dbase = blockIdx.x * DTILE;
    const int d    = dbase + j;               // may exceed 511 on last tile
    const bool valid = (d < TD);
    const int cbase = half * HCHUNK;          // this warp's first chunk

    // one-time staging: uh row for each of the 7 d's, and v
    if (w < NPAIR) {
        float4 u = make_float4(0.f,0.f,0.f,0.f);
        if (valid) u = ((const float4*)g_Uh)[(b * TD + d) * 32 + lane];
        uh_s[w * 32 + lane] = u;
    }
    if (w == NPAIR) v_s[lane] = ((const float4*)Va)[lane];

    float m = -CUDART_INF_F;
    float l = 0.f;                             // per-lane partial
    float4 cacc = make_float4(0.f,0.f,0.f,0.f);
    float lgbuf[HCHUNK];

    const float4* wsrc_b = (const float4*)(g_Ws + (long)b * TE * HH);
    const float4* esrc_b = (const float4*)(enc  + (long)b * TE * HH);

    // staging: 2048 float4 slots/iter (A: chunk k, B: chunk k+16), 5/thread
    const int s0 = tid, s1 = tid + 448, s2 = tid + 896, s3 = tid + 1344, s4 = tid + 1792;
    const bool has4 = (s4 < 2048);
    float4 r0v, r1v, r2v, r3v, r4v;

    #define SLOT_SRC(s, k) ((((s) < 1024 ? (k) : (k) + HCHUNK) << 10) + ((s) & 1023))
    #define SLOT_DST(s) (((s) < 1024 ? wsA : wsB)[((((s) & 1023) >> 5) * ROWPAD) + ((s) & 31)])

    // prefetch chunk-pair 0
    r0v = wsrc_b[SLOT_SRC(s0, 0)]; r1v = wsrc_b[SLOT_SRC(s1, 0)];
    r2v = wsrc_b[SLOT_SRC(s2, 0)]; r3v = wsrc_b[SLOT_SRC(s3, 0)];
    if (has4) r4v = wsrc_b[SLOT_SRC(s4, 0)];

    const float4* mybuf = half ? wsB : wsA;
    const float4* urow  = uh_s + j * 32;
    float* prow = p_s + w * 32;

    #pragma unroll 1
    for (int k = 0; k < HCHUNK; ++k) {
        __syncthreads();   // previous iteration's consumers done
        SLOT_DST(s0) = r0v; SLOT_DST(s1) = r1v; SLOT_DST(s2) = r2v; SLOT_DST(s3) = r3v;
        if (has4) SLOT_DST(s4) = r4v;
        __syncthreads();

        // prefetch next chunk-pair (in flight during compute)
        if (k + 1 < HCHUNK) {
            r0v = wsrc_b[SLOT_SRC(s0, k + 1)]; r1v = wsrc_b[SLOT_SRC(s1, k + 1)];
            r2v = wsrc_b[SLOT_SRC(s2, k + 1)]; r3v = wsrc_b[SLOT_SRC(s3, k + 1)];
            if (has4) r4v = wsrc_b[SLOT_SRC(s4, k + 1)];
        }

        // ---- Phase 1: lane = t. One logit per lane ----
        float4 a0 = make_float4(0.f,0.f,0.f,0.f);
        const float4* wsrow = mybuf + lane * ROWPAD;
        #pragma unroll 8
        for (int hq = 0; hq < 32; ++hq) {
            float4 ws = wsrow[hq];          // conflict-free
            float4 u  = urow[hq];           // broadcast
            float4 vv = v_s[hq];            // broadcast
            a0.x = fmaf(vv.x, tanh_fast(ws.x + u.x), a0.x);
            a0.y = fmaf(vv.y, tanh_fast(ws.y + u.y), a0.y);
            a0.z = fmaf(vv.z, tanh_fast(ws.z + u.z), a0.z);
            a0.w = fmaf(vv.w, tanh_fast(ws.w + u.w), a0.w);
        }
        const float lgt = (a0.x + a0.y) + (a0.z + a0.w);
        lgbuf[k] = lgt;

        // ---- Online softmax (warp scope) ----
        float cm = lgt;
        #pragma unroll
        for (int off = 16; off > 0; off >>= 1)
            cm = fmaxf(cm, __shfl_xor_sync(0xffffffffu, cm, off));
        if (cm > m) {                         // warp-uniform
            float corr = __expf(m - cm);      // first iter: exp(-inf) = 0
            l *= corr;
            cacc.x *= corr; cacc.y *= corr; cacc.z *= corr; cacc.w *= corr;
            m = cm;
        }
        float p = __expf(lgt - m);
        l += p;
        prow[lane] = p;
        __syncwarp();

        // ---- Context: lane = h-quad; enc via direct LDG (L1-hot) ----
        const float4* encrow = esrc_b + (cbase + k) * (TCHUNK * 32);
        #pragma unroll 8
        for (int tt = 0; tt < TCHUNK; ++tt) {
            float pt = prow[tt];
            float4 ev = encrow[tt * 32 + lane];
            cacc.x = fmaf(pt, ev.x, cacc.x);
            cacc.y = fmaf(pt, ev.y, cacc.y);
            cacc.z = fmaf(pt, ev.z, cacc.z);
            cacc.w = fmaf(pt, ev.w, cacc.w);
        }
        __syncwarp();   // prow consumed before next iteration overwrites
    }

    // reduce per-lane l partials within the warp
    #pragma unroll
    for (int off = 16; off > 0; off >>= 1)
        l += __shfl_xor_sync(0xffffffffu, l, off);

    // ---- Cross-warp merge of (m, l, C) between warp j and j+7 ----
    // Reuse the (now dead) wsA staging region for merge buffers.
    __syncthreads();
    float*  mg  = (float*)(sm + WSA_OFF);          // [14][2]: m, l
    float4* mgc = (float4*)(sm + WSA_OFF + 128);   // [14][32] float4: cacc
    if (lane == 0) { mg[w * 2 + 0] = m; mg[w * 2 + 1] = l; }
    mgc[w * 32 + lane] = cacc;
    __syncthreads();

    const int partner = half ? w - NPAIR : w + NPAIR;
    float pm = mg[partner * 2 + 0];
    float pl = mg[partner * 2 + 1];
    float4 pc = mgc[partner * 32 + lane];

    const float M  = fmaxf(m, pm);
    const float sa = __expf(m - M), sb = __expf(pm - M);
    const float L  = l * sa + pl * sb;
    const float invl = 1.0f / L;

    if (!valid) return;   // past all barriers

    // combined context store: lower warp only (values identical on both)
    if (!half) {
        float4 co;
        co.x = (cacc.x * sa + pc.x * sb) * invl;
        co.y = (cacc.y * sa + pc.y * sb) * invl;
        co.z = (cacc.z * sa + pc.z * sb) * invl;
        co.w = (cacc.w * sa + pc.w * sb) * invl;
        ((float4*)c_out)[(b * TD + d) * 32 + lane] = co;
    }

    // attention weights: each warp writes its own 16 chunks with final (M, L)
    float* erow = e_out + (long)(b * TD + d) * TE + cbase * TCHUNK;
    #pragma unroll 1
    for (int k = 0; k < HCHUNK; ++k)
        erow[k * TCHUNK + lane] = __expf(lgbuf[k] - M) * invl;
}

// ---------------------------------------------------------------------------
extern "C" void kernel_launch(void* const* d_in, const int* in_sizes, int n_in,
                              void* d_out, int out_size)
{
    const float* enc = (const float*)d_in[0];   // [B, TE, H]
    const float* dec = (const float*)d_in[1];   // [B, TD, H]
    const float* W_a = (const float*)d_in[2];   // [H, H]
    const float* U_a = (const float*)d_in[3];   // [H, H]
    const float* V_a = (const float*)d_in[4];   // [H, 1]

    float* c_out = (float*)d_out;                        // [B, TD, H]
    float* e_out = (float*)d_out + (long)BB * TD * HH;   // [B, TD, TE]

    // Stage 1: both projections (192 CTAs x 8 warps x 4 rows = 6144 rows)
    proj_all_kernel<<<(BB * (TE + TD)) / 4 / 8, 256>>>(enc, dec, W_a, U_a);

    // Stage 2: fused attention (296 CTAs = 2 per SM, ~39 KB static smem)
    dim3 grid(NTILES, BB);
    attn_main_kernel<<<grid, NTHREADS>>>(enc, V_a, c_out, e_out);
}

// round 10
// speedup vs baseline: 1.2010x; 1.2010x over previous
#include <cuda_runtime.h>
#include <math_constants.h>

#define BB 4
#define TE 1024
#define TD 512
#define HH 128
#define DTILE 14        // d's per CTA: 7 pairs x (2 d's per warp)
#define NPAIR 7
#define NW 28           // warps per CTA: 7 pairs x 4 t-quarters
#define NTILES 37       // ceil(512/14); 4*37 = 148 CTAs = 1 per SM
#define TCHUNK 32
#define NCHUNK 32
#define QCHUNK 8        // chunks per t-quarter
#define NTHREADS (NW * 32)          // 896

// dynamic smem: 4 ws buffers (4*1024 f4) + uh (448 f4) + v (32 f4) + p (448 f4)
#define UH_F4   4096
#define V_F4    (4096 + 448)
#define P_F4    (4096 + 448 + 32)
#define SMEM_BYTES ((4096 + 448 + 32 + 448) * 16)   // 80384

// Scratch (statically allocated; no cudaMalloc allowed anywhere)
__device__ float g_Ws[BB * TE * HH];   // enc @ W_a
__device__ float g_Uh[BB * TD * HH];   // dec @ U_a

__device__ __forceinline__ float tanh_fast(float x) {
    float y;
    asm("tanh.approx.f32 %0, %1;" : "=f"(y) : "f"(x));
    return y;
}

// ---------------------------------------------------------------------------
// Stage 1 (fused): rows 0..4095 -> g_Ws = enc @ W_a; rows 4096..6143 -> g_Uh.
// 4 rows per warp; a-loads vectorized (float4 per 4 h).
// ---------------------------------------------------------------------------
__global__ __launch_bounds__(256) void proj_all_kernel(
    const float* __restrict__ enc, const float* __restrict__ dec,
    const float* __restrict__ Wa,  const float* __restrict__ Ua)
{
    const int w    = threadIdx.x >> 5;
    const int lane = threadIdx.x & 31;
    const int gw   = blockIdx.x * 8 + w;      // 0..1535
    int r0 = gw * 4;

    const float* in; const float* W; float* out;
    if (r0 < BB * TE) { in = enc; W = Wa; out = g_Ws; }
    else              { r0 -= BB * TE; in = dec; W = Ua; out = g_Uh; }

    const float4* in4 = (const float4*)in;
    const float4* W4  = (const float4*)W;

    float4 acc0 = make_float4(0.f,0.f,0.f,0.f);
    float4 acc1 = acc0, acc2 = acc0, acc3 = acc0;

    #pragma unroll 4
    for (int hg = 0; hg < HH / 4; ++hg) {
        float4 a0 = in4[(r0 + 0) * 32 + hg];
        float4 a1 = in4[(r0 + 1) * 32 + hg];
        float4 a2 = in4[(r0 + 2) * 32 + hg];
        float4 a3 = in4[(r0 + 3) * 32 + hg];
        #pragma unroll
        for (int j = 0; j < 4; ++j) {
            float4 wv = W4[(hg * 4 + j) * 32 + lane];
            float s0 = (j == 0) ? a0.x : (j == 1) ? a0.y : (j == 2) ? a0.z : a0.w;
            float s1 = (j == 0) ? a1.x : (j == 1) ? a1.y : (j == 2) ? a1.z : a1.w;
            float s2 = (j == 0) ? a2.x : (j == 1) ? a2.y : (j == 2) ? a2.z : a2.w;
            float s3 = (j == 0) ? a3.x : (j == 1) ? a3.y : (j == 2) ? a3.z : a3.w;
            acc0.x = fmaf(s0, wv.x, acc0.x); acc0.y = fmaf(s0, wv.y, acc0.y);
            acc0.z = fmaf(s0, wv.z, acc0.z); acc0.w = fmaf(s0, wv.w, acc0.w);
            acc1.x = fmaf(s1, wv.x, acc1.x); acc1.y = fmaf(s1, wv.y, acc1.y);
            acc1.z = fmaf(s1, wv.z, acc1.z); acc1.w = fmaf(s1, wv.w, acc1.w);
            acc2.x = fmaf(s2, wv.x, acc2.x); acc2.y = fmaf(s2, wv.y, acc2.y);
            acc2.z = fmaf(s2, wv.z, acc2.z); acc2.w = fmaf(s2, wv.w, acc2.w);
            acc3.x = fmaf(s3, wv.x, acc3.x); acc3.y = fmaf(s3, wv.y, acc3.y);
            acc3.z = fmaf(s3, wv.z, acc3.z); acc3.w = fmaf(s3, wv.w, acc3.w);
        }
    }
    ((float4*)out)[(r0 + 0) * 32 + lane] = acc0;
    ((float4*)out)[(r0 + 1) * 32 + lane] = acc1;
    ((float4*)out)[(r0 + 2) * 32 + lane] = acc2;
    ((float4*)out)[(r0 + 3) * 32 + lane] = acc3;
}

// ---------------------------------------------------------------------------
// Stage 2: 28 warps = 7 d-pairs x 4 t-quarters. Warp w: pair j = w%7 owns
// (d0 = tile*14+j, d1 = d0+7); quarter q = w/7 covers chunks q*8..q*8+7 from
// XOR-swizzled buffer q. Flash partials merged 4-way across the quad at end.
// ---------------------------------------------------------------------------
__global__ __launch_bounds__(NTHREADS, 1) void attn_main_kernel(
    const float* __restrict__ enc,   // [B, TE, H]
    const float* __restrict__ Va,    // [H]
    float* __restrict__ c_out,       // [B, TD, H]
    float* __restrict__ e_out)       // [B, TD, TE]
{
    extern __shared__ float4 wsb[];          // [4][1024] swizzled + uh + v + p
    float4* uh_s = wsb + UH_F4;              // 14 rows x 32
    float4* v_s  = wsb + V_F4;
    float*  p_s  = (float*)(wsb + P_F4);     // [28][64]

    const int tid  = threadIdx.x;
    const int w    = tid >> 5;
    const int lane = tid & 31;
    const int q    = w / NPAIR;              // t-quarter 0..3
    const int j    = w % NPAIR;              // d-pair index 0..6
    const int b    = blockIdx.y;
    const int dbase = blockIdx.x * DTILE;
    const int d0   = dbase + j;              // max 510
    const int d1   = d0 + NPAIR;
    const bool valid1 = (d1 < TD);

    // one-time staging: uh rows 0..13 (warp w<14 loads row w) and v
    if (w < DTILE) {
        int dw = dbase + w;
        float4 u = make_float4(0.f,0.f,0.f,0.f);
        if (dw < TD) u = ((const float4*)g_Uh)[(b * TD + dw) * 32 + lane];
        uh_s[w * 32 + lane] = u;
    }
    if (w == DTILE) v_s[lane] = ((const float4*)Va)[lane];

    float m0 = -CUDART_INF_F, m1 = -CUDART_INF_F;
    float l0 = 0.f, l1 = 0.f;                // per-lane partials
    float4 cacc0 = make_float4(0.f,0.f,0.f,0.f);
    float4 cacc1 = cacc0;
    float lgbuf0[QCHUNK], lgbuf1[QCHUNK];

    const float4* wsrc_b = (const float4*)(g_Ws + (long)b * TE * HH);
    const float4* esrc_b = (const float4*)(enc  + (long)b * TE * HH);

    // staging: 4096 float4 slots/iter (buffer u>>10 gets chunk (u>>10)*8+k)
    const int s0 = tid, s1 = tid + 896, s2 = tid + 1792, s3 = tid + 2688, s4 = tid + 3584;
    const bool has4 = (s4 < 4096);
    float4 r0v, r1v, r2v, r3v, r4v;

    // src global float4 index for slot u at iter k
    #define SLOT_SRC(u, k) ((((u) >> 10) * QCHUNK + (k)) * 1024 + ((u) & 1023))
    // dst: buffer (u>>10), row r = (u>>5)&31, col c = u&31, swizzled c^r
    #define SLOT_DST(u) (wsb[(((u) >> 10) << 10) + ((((u) >> 5) & 31) << 5) + ((((u) & 31)) ^ (((u) >> 5) & 31))])

    // prefetch iter 0
    r0v = wsrc_b[SLOT_SRC(s0, 0)]; r1v = wsrc_b[SLOT_SRC(s1, 0)];
    r2v = wsrc_b[SLOT_SRC(s2, 0)]; r3v = wsrc_b[SLOT_SRC(s3, 0)];
    if (has4) r4v = wsrc_b[SLOT_SRC(s4, 0)];

    const float4* myws  = wsb + q * 1024;
    const float4* u0row = uh_s + j * 32;
    const float4* u1row = uh_s + (j + NPAIR) * 32;
    float* prow = p_s + w * 64;

    #pragma unroll 1
    for (int k = 0; k < QCHUNK; ++k) {
        __syncthreads();   // previous iteration's consumers done
        SLOT_DST(s0) = r0v; SLOT_DST(s1) = r1v; SLOT_DST(s2) = r2v; SLOT_DST(s3) = r3v;
        if (has4) SLOT_DST(s4) = r4v;
        __syncthreads();

        // prefetch next iteration (in flight during compute)
        if (k + 1 < QCHUNK) {
            r0v = wsrc_b[SLOT_SRC(s0, k + 1)]; r1v = wsrc_b[SLOT_SRC(s1, k + 1)];
            r2v = wsrc_b[SLOT_SRC(s2, k + 1)]; r3v = wsrc_b[SLOT_SRC(s3, k + 1)];
            if (has4) r4v = wsrc_b[SLOT_SRC(s4, k + 1)];
        }

        // ---- Phase 1: lane = t. Two logits per lane (d0, d1) ----
        float4 a0 = make_float4(0.f,0.f,0.f,0.f);
        float4 a1 = a0;
        #pragma unroll 8
        for (int hq = 0; hq < 32; ++hq) {
            float4 ws = myws[lane * 32 + (hq ^ lane)];   // swizzled, conflict-free
            float4 u0 = u0row[hq];          // broadcast
            float4 u1 = u1row[hq];          // broadcast
            float4 vv = v_s[hq];            // broadcast
            a0.x = fmaf(vv.x, tanh_fast(ws.x + u0.x), a0.x);
            a1.x = fmaf(vv.x, tanh_fast(ws.x + u1.x), a1.x);
            a0.y = fmaf(vv.y, tanh_fast(ws.y + u0.y), a0.y);
            a1.y = fmaf(vv.y, tanh_fast(ws.y + u1.y), a1.y);
            a0.z = fmaf(vv.z, tanh_fast(ws.z + u0.z), a0.z);
            a1.z = fmaf(vv.z, tanh_fast(ws.z + u1.z), a1.z);
            a0.w = fmaf(vv.w, tanh_fast(ws.w + u0.w), a0.w);
            a1.w = fmaf(vv.w, tanh_fast(ws.w + u1.w), a1.w);
        }
        const float lgt0 = (a0.x + a0.y) + (a0.z + a0.w);
        const float lgt1 = (a1.x + a1.y) + (a1.z + a1.w);
        lgbuf0[k] = lgt0;
        lgbuf1[k] = lgt1;

        // ---- Online softmax (warp scope, both d's) ----
        float cm0 = lgt0, cm1 = lgt1;
        #pragma unroll
        for (int off = 16; off > 0; off >>= 1) {
            cm0 = fmaxf(cm0, __shfl_xor_sync(0xffffffffu, cm0, off));
            cm1 = fmaxf(cm1, __shfl_xor_sync(0xffffffffu, cm1, off));
        }
        if (cm0 > m0) {
            float corr = __expf(m0 - cm0);    // first iter: exp(-inf) = 0
            l0 *= corr;
            cacc0.x *= corr; cacc0.y *= corr; cacc0.z *= corr; cacc0.w *= corr;
            m0 = cm0;
        }
        if (cm1 > m1) {
            float corr = __expf(m1 - cm1);
            l1 *= corr;
            cacc1.x *= corr; cacc1.y *= corr; cacc1.z *= corr; cacc1.w *= corr;
            m1 = cm1;
        }
        float p0 = __expf(lgt0 - m0);
        float p1 = __expf(lgt1 - m1);
        l0 += p0; l1 += p1;
        prow[lane]      = p0;
        prow[32 + lane] = p1;
        __syncwarp();

        // ---- Context: lane = h-quad; enc via direct LDG (L2/L1-hot) ----
        const float4* encrow = esrc_b + (q * QCHUNK + k) * (TCHUNK * 32);
        #pragma unroll 8
        for (int tt = 0; tt < TCHUNK; ++tt) {
            float pt0 = prow[tt];
            float pt1 = prow[32 + tt];
            float4 ev = encrow[tt * 32 + lane];
            cacc0.x = fmaf(pt0, ev.x, cacc0.x);
            cacc0.y = fmaf(pt0, ev.y, cacc0.y);
            cacc0.z = fmaf(pt0, ev.z, cacc0.z);
            cacc0.w = fmaf(pt0, ev.w, cacc0.w);
            cacc1.x = fmaf(pt1, ev.x, cacc1.x);
            cacc1.y = fmaf(pt1, ev.y, cacc1.y);
            cacc1.z = fmaf(pt1, ev.z, cacc1.z);
            cacc1.w = fmaf(pt1, ev.w, cacc1.w);
        }
        __syncwarp();   // prow consumed before next iteration overwrites
    }

    // reduce per-lane l partials within the warp
    #pragma unroll
    for (int off = 16; off > 0; off >>= 1) {
        l0 += __shfl_xor_sync(0xffffffffu, l0, off);
        l1 += __shfl_xor_sync(0xffffffffu, l1, off);
    }

    // ---- 4-way merge of (m, l, C) across quad {j, j+7, j+14, j+21} ----
    __syncthreads();                        // staging region now dead
    float*  mg  = (float*)wsb;              // [28][4]: m0, m1, l0, l1
    float4* mgc = wsb + 64;                 // [28][64] float4: cacc0 | cacc1
    if (lane == 0) {
        mg[w * 4 + 0] = m0; mg[w * 4 + 1] = m1;
        mg[w * 4 + 2] = l0; mg[w * 4 + 3] = l1;
    }
    mgc[w * 64 + lane]      = cacc0;
    mgc[w * 64 + 32 + lane] = cacc1;
    __syncthreads();

    // gather quad partials (lane-uniform scalar reads)
    float qm0[4], qm1[4], ql0[4], ql1[4];
    #pragma unroll
    for (int t = 0; t < 4; ++t) {
        int ww = j + t * NPAIR;
        qm0[t] = mg[ww * 4 + 0]; qm1[t] = mg[ww * 4 + 1];
        ql0[t] = mg[ww * 4 + 2]; ql1[t] = mg[ww * 4 + 3];
    }
    float M0 = fmaxf(fmaxf(qm0[0], qm0[1]), fmaxf(qm0[2], qm0[3]));
    float M1 = fmaxf(fmaxf(qm1[0], qm1[1]), fmaxf(qm1[2], qm1[3]));
    float L0 = 0.f, L1 = 0.f;
    float sc0[4], sc1[4];
    #pragma unroll
    for (int t = 0; t < 4; ++t) {
        sc0[t] = __expf(qm0[t] - M0);  L0 = fmaf(ql0[t], sc0[t], L0);
        sc1[t] = __expf(qm1[t] - M1);  L1 = fmaf(ql1[t], sc1[t], L1);
    }
    const float invl0 = 1.0f / L0;
    const float invl1 = 1.0f / L1;

    // combined context store: quarter-0 warps only
    if (q == 0) {
        float4 C0 = make_float4(0.f,0.f,0.f,0.f);
        float4 C1 = C0;
        #pragma unroll
        for (int t = 0; t < 4; ++t) {
            int ww = j + t * NPAIR;
            float4 c0 = mgc[ww * 64 + lane];
            float4 c1 = mgc[ww * 64 + 32 + lane];
            C0.x = fmaf(c0.x, sc0[t], C0.x); C0.y = fmaf(c0.y, sc0[t], C0.y);
            C0.z = fmaf(c0.z, sc0[t], C0.z); C0.w = fmaf(c0.w, sc0[t], C0.w);
            C1.x = fmaf(c1.x, sc1[t], C1.x); C1.y = fmaf(c1.y, sc1[t], C1.y);
            C1.z = fmaf(c1.z, sc1[t], C1.z); C1.w = fmaf(c1.w, sc1[t], C1.w);
        }
        float4 co;
        co.x = C0.x * invl0; co.y = C0.y * invl0;
        co.z = C0.z * invl0; co.w = C0.w * invl0;
        ((float4*)c_out)[(b * TD + d0) * 32 + lane] = co;
        if (valid1) {
            co.x = C1.x * invl1; co.y = C1.y * invl1;
            co.z = C1.z * invl1; co.w = C1.w * invl1;
            ((float4*)c_out)[(b * TD + d1) * 32 + lane] = co;
        }
    }

    // attention weights: each warp writes its own 8 chunks with final (M, L)
    float* erow0 = e_out + (long)(b * TD + d0) * TE + q * (QCHUNK * TCHUNK);
    float* erow1 = e_out + (long)(b * TD + d1) * TE + q * (QCHUNK * TCHUNK);
    #pragma unroll 1
    for (int k = 0; k < QCHUNK; ++k) {
        erow0[k * TCHUNK + lane] = __expf(lgbuf0[k] - M0) * invl0;
        if (valid1)
            erow1[k * TCHUNK + lane] = __expf(lgbuf1[k] - M1) * invl1;
    }
}

// ---------------------------------------------------------------------------
extern "C" void kernel_launch(void* const* d_in, const int* in_sizes, int n_in,
                              void* d_out, int out_size)
{
    const float* enc = (const float*)d_in[0];   // [B, TE, H]
    const float* dec = (const float*)d_in[1];   // [B, TD, H]
    const float* W_a = (const float*)d_in[2];   // [H, H]
    const float* U_a = (const float*)d_in[3];   // [H, H]
    const float* V_a = (const float*)d_in[4];   // [H, 1]

    float* c_out = (float*)d_out;                        // [B, TD, H]
    float* e_out = (float*)d_out + (long)BB * TD * HH;   // [B, TD, TE]

    // dynamic-smem opt-in (unconditional: deterministic, no static guard,
    // not an allocation; idempotent under graph capture)
    cudaFuncSetAttribute(attn_main_kernel,
                         cudaFuncAttributeMaxDynamicSharedMemorySize, SMEM_BYTES);

    // Stage 1: both projections (192 CTAs x 8 warps x 4 rows = 6144 rows)
    proj_all_kernel<<<(BB * (TE + TD)) / 4 / 8, 256>>>(enc, dec, W_a, U_a);

    // Stage 2: fused attention (148 CTAs = 1 per SM, 28 warps, 80 KB dyn smem)
    dim3 grid(NTILES, BB);
    attn_main_kernel<<<grid, NTHREADS, SMEM_BYTES>>>(enc, V_a, c_out, e_out);
}

// round 11
// speedup vs baseline: 1.3499x; 1.1240x over previous
#include <cuda_runtime.h>
#include <math_constants.h>

#define BB 4
#define TE 1024
#define TD 512
#define HH 128
#define DTILE 14        // d's per CTA: 7 pairs x (2 d's per warp)
#define NPAIR 7
#define NW 28           // warps per CTA: 7 pairs x 4 t-quarters
#define NTILES 37       // ceil(512/14); 4*37 = 148 CTAs = 1 per SM
#define TCHUNK 32
#define QCHUNK 8        // chunks per t-quarter
#define NTHREADS (NW * 32)          // 896

// Scratch (statically allocated; no cudaMalloc allowed anywhere)
// g_Ws is stored BLOCK-TRANSPOSED: float4 index [b*32 + t/32][hq][t%32],
// i.e. ((b*32 + t/32)*32 + hq)*32 + (t%32). This makes the attn phase-1
// read (lane = t) a perfectly coalesced LDG.128 — no smem staging needed.
__device__ float g_Ws[BB * TE * HH];
__device__ float g_Uh[BB * TD * HH];   // row layout: [row][h]

__device__ __forceinline__ float tanh_fast(float x) {
    float y;
    asm("tanh.approx.f32 %0, %1;" : "=f"(y) : "f"(x));
    return y;
}

// ---------------------------------------------------------------------------
// Stage 1 (fused): rows 0..4095 -> g_Ws (blocked-transposed) = enc @ W_a;
// rows 4096..6143 -> g_Uh (row layout) = dec @ U_a. 4 rows/warp.
// ---------------------------------------------------------------------------
__global__ __launch_bounds__(256) void proj_all_kernel(
    const float* __restrict__ enc, const float* __restrict__ dec,
    const float* __restrict__ Wa,  const float* __restrict__ Ua)
{
    const int w    = threadIdx.x >> 5;
    const int lane = threadIdx.x & 31;
    const int gw   = blockIdx.x * 8 + w;      // 0..1535
    int r0 = gw * 4;

    const bool isWs = (r0 < BB * TE);
    const float* in; const float* W;
    if (isWs) { in = enc; W = Wa; }
    else      { r0 -= BB * TE; in = dec; W = Ua; }

    const float4* in4 = (const float4*)in;
    const float4* W4  = (const float4*)W;

    float4 acc0 = make_float4(0.f,0.f,0.f,0.f);
    float4 acc1 = acc0, acc2 = acc0, acc3 = acc0;

    #pragma unroll 4
    for (int hg = 0; hg < HH / 4; ++hg) {
        float4 a0 = in4[(r0 + 0) * 32 + hg];
        float4 a1 = in4[(r0 + 1) * 32 + hg];
        float4 a2 = in4[(r0 + 2) * 32 + hg];
        float4 a3 = in4[(r0 + 3) * 32 + hg];
        #pragma unroll
        for (int j = 0; j < 4; ++j) {
            float4 wv = W4[(hg * 4 + j) * 32 + lane];
            float s0 = (j == 0) ? a0.x : (j == 1) ? a0.y : (j == 2) ? a0.z : a0.w;
            float s1 = (j == 0) ? a1.x : (j == 1) ? a1.y : (j == 2) ? a1.z : a1.w;
            float s2 = (j == 0) ? a2.x : (j == 1) ? a2.y : (j == 2) ? a2.z : a2.w;
            float s3 = (j == 0) ? a3.x : (j == 1) ? a3.y : (j == 2) ? a3.z : a3.w;
            acc0.x = fmaf(s0, wv.x, acc0.x); acc0.y = fmaf(s0, wv.y, acc0.y);
            acc0.z = fmaf(s0, wv.z, acc0.z); acc0.w = fmaf(s0, wv.w, acc0.w);
            acc1.x = fmaf(s1, wv.x, acc1.x); acc1.y = fmaf(s1, wv.y, acc1.y);
            acc1.z = fmaf(s1, wv.z, acc1.z); acc1.w = fmaf(s1, wv.w, acc1.w);
            acc2.x = fmaf(s2, wv.x, acc2.x); acc2.y = fmaf(s2, wv.y, acc2.y);
            acc2.z = fmaf(s2, wv.z, acc2.z); acc2.w = fmaf(s2, wv.w, acc2.w);
            acc3.x = fmaf(s3, wv.x, acc3.x); acc3.y = fmaf(s3, wv.y, acc3.y);
            acc3.z = fmaf(s3, wv.z, acc3.z); acc3.w = fmaf(s3, wv.w, acc3.w);
        }
    }
    if (isWs) {
        // blocked-transposed store: slot ((r>>5)*32 + lane)*32 + (r&31)
        float4* out4 = (float4*)g_Ws;
        const int blk = (r0 >> 5) * 32 + lane;   // same block for r0..r0+3
        out4[blk * 32 + ((r0 + 0) & 31)] = acc0;
        out4[blk * 32 + ((r0 + 1) & 31)] = acc1;
        out4[blk * 32 + ((r0 + 2) & 31)] = acc2;
        out4[blk * 32 + ((r0 + 3) & 31)] = acc3;
    } else {
        float4* out4 = (float4*)g_Uh;
        out4[(r0 + 0) * 32 + lane] = acc0;
        out4[(r0 + 1) * 32 + lane] = acc1;
        out4[(r0 + 2) * 32 + lane] = acc2;
        out4[(r0 + 3) * 32 + lane] = acc3;
    }
}

// ---------------------------------------------------------------------------
// Stage 2: 28 warps = 7 d-pairs x 4 t-quarters; NO smem staging, NO loop
// barriers. Phase-1 reads blocked-transposed g_Ws via coalesced LDG.128
// (L1-hot across the 7 warps of each quarter). Flash partials merged 4-way
// across the quad at the end (single __syncthreads pair).
// ---------------------------------------------------------------------------
__global__ __launch_bounds__(NTHREADS, 1) void attn_main_kernel(
    const float* __restrict__ enc,   // [B, TE, H]
    const float* __restrict__ Va,    // [H]
    float* __restrict__ c_out,       // [B, TD, H]
    float* __restrict__ e_out)       // [B, TD, TE]
{
    __shared__ float4 uh_s[DTILE * 32];      // 7 KB
    __shared__ float4 v_s [32];              // 0.5 KB
    __shared__ float  p_s [NW * 64];         // 7 KB
    __shared__ float  mg  [NW * 4];          // m0, m1, l0, l1
    __shared__ float4 mgc [NW * 64];         // 28 KB: cacc0 | cacc1

    const int tid  = threadIdx.x;
    const int w    = tid >> 5;
    const int lane = tid & 31;
    const int q    = w / NPAIR;              // t-quarter 0..3
    const int j    = w % NPAIR;              // d-pair index 0..6
    const int b    = blockIdx.y;
    const int dbase = blockIdx.x * DTILE;
    const int d0   = dbase + j;              // max 510
    const int d1   = d0 + NPAIR;
    const bool valid1 = (d1 < TD);

    // one-time staging: uh rows 0..13 and v
    if (w < DTILE) {
        int dw = dbase + w;
        float4 u = make_float4(0.f,0.f,0.f,0.f);
        if (dw < TD) u = ((const float4*)g_Uh)[(b * TD + dw) * 32 + lane];
        uh_s[w * 32 + lane] = u;
    }
    if (w == DTILE) v_s[lane] = ((const float4*)Va)[lane];
    __syncthreads();

    float m0 = -CUDART_INF_F, m1 = -CUDART_INF_F;
    float l0 = 0.f, l1 = 0.f;                // per-lane partials
    float4 cacc0 = make_float4(0.f,0.f,0.f,0.f);
    float4 cacc1 = cacc0;
    float lgbuf0[QCHUNK], lgbuf1[QCHUNK];

    const float4* wsblk  = (const float4*)g_Ws + (long)b * 32 * 32 * 32;
    const float4* esrc_b = (const float4*)(enc + (long)b * TE * HH);
    const float4* u0row  = uh_s + j * 32;
    const float4* u1row  = uh_s + (j + NPAIR) * 32;
    float* prow = p_s + w * 64;

    #pragma unroll 1
    for (int k = 0; k < QCHUNK; ++k) {
        const int chunk = q * QCHUNK + k;
        const float4* wschunk = wsblk + chunk * 1024;

        // ---- Phase 1: lane = t. Two logits per lane (d0, d1) ----
        float4 a0 = make_float4(0.f,0.f,0.f,0.f);
        float4 a1 = a0;
        #pragma unroll 8
        for (int hq = 0; hq < 32; ++hq) {
            float4 ws = wschunk[hq * 32 + lane];   // coalesced LDG.128, L1-hot
            float4 u0 = u0row[hq];          // smem broadcast
            float4 u1 = u1row[hq];          // smem broadcast
            float4 vv = v_s[hq];            // smem broadcast
            a0.x = fmaf(vv.x, tanh_fast(ws.x + u0.x), a0.x);
            a1.x = fmaf(vv.x, tanh_fast(ws.x + u1.x), a1.x);
            a0.y = fmaf(vv.y, tanh_fast(ws.y + u0.y), a0.y);
            a1.y = fmaf(vv.y, tanh_fast(ws.y + u1.y), a1.y);
            a0.z = fmaf(vv.z, tanh_fast(ws.z + u0.z), a0.z);
            a1.z = fmaf(vv.z, tanh_fast(ws.z + u1.z), a1.z);
            a0.w = fmaf(vv.w, tanh_fast(ws.w + u0.w), a0.w);
            a1.w = fmaf(vv.w, tanh_fast(ws.w + u1.w), a1.w);
        }
        const float lgt0 = (a0.x + a0.y) + (a0.z + a0.w);
        const float lgt1 = (a1.x + a1.y) + (a1.z + a1.w);
        lgbuf0[k] = lgt0;
        lgbuf1[k] = lgt1;

        // ---- Online softmax (warp scope, both d's) ----
        float cm0 = lgt0, cm1 = lgt1;
        #pragma unroll
        for (int off = 16; off > 0; off >>= 1) {
            cm0 = fmaxf(cm0, __shfl_xor_sync(0xffffffffu, cm0, off));
            cm1 = fmaxf(cm1, __shfl_xor_sync(0xffffffffu, cm1, off));
        }
        if (cm0 > m0) {
            float corr = __expf(m0 - cm0);    // first iter: exp(-inf) = 0
            l0 *= corr;
            cacc0.x *= corr; cacc0.y *= corr; cacc0.z *= corr; cacc0.w *= corr;
            m0 = cm0;
        }
        if (cm1 > m1) {
            float corr = __expf(m1 - cm1);
            l1 *= corr;
            cacc1.x *= corr; cacc1.y *= corr; cacc1.z *= corr; cacc1.w *= corr;
            m1 = cm1;
        }
        float p0 = __expf(lgt0 - m0);
        float p1 = __expf(lgt1 - m1);
        l0 += p0; l1 += p1;
        prow[lane]      = p0;
        prow[32 + lane] = p1;
        __syncwarp();

        // ---- Context: lane = h-quad; enc via direct LDG (L1-hot) ----
        const float4* encrow = esrc_b + chunk * (TCHUNK * 32);
        #pragma unroll 8
        for (int tt = 0; tt < TCHUNK; ++tt) {
            float pt0 = prow[tt];
            float pt1 = prow[32 + tt];
            float4 ev = encrow[tt * 32 + lane];
            cacc0.x = fmaf(pt0, ev.x, cacc0.x);
            cacc0.y = fmaf(pt0, ev.y, cacc0.y);
            cacc0.z = fmaf(pt0, ev.z, cacc0.z);
            cacc0.w = fmaf(pt0, ev.w, cacc0.w);
            cacc1.x = fmaf(pt1, ev.x, cacc1.x);
            cacc1.y = fmaf(pt1, ev.y, cacc1.y);
            cacc1.z = fmaf(pt1, ev.z, cacc1.z);
            cacc1.w = fmaf(pt1, ev.w, cacc1.w);
        }
        __syncwarp();   // prow consumed before next iteration overwrites
    }

    // reduce per-lane l partials within the warp
    #pragma unroll
    for (int off = 16; off > 0; off >>= 1) {
        l0 += __shfl_xor_sync(0xffffffffu, l0, off);
        l1 += __shfl_xor_sync(0xffffffffu, l1, off);
    }

    // ---- 4-way merge of (m, l, C) across quad {j, j+7, j+14, j+21} ----
    if (lane == 0) {
        mg[w * 4 + 0] = m0; mg[w * 4 + 1] = m1;
        mg[w * 4 + 2] = l0; mg[w * 4 + 3] = l1;
    }
    mgc[w * 64 + lane]      = cacc0;
    mgc[w * 64 + 32 + lane] = cacc1;
    __syncthreads();

    float qm0[4], qm1[4], ql0[4], ql1[4];
    #pragma unroll
    for (int t = 0; t < 4; ++t) {
        int ww = j + t * NPAIR;
        qm0[t] = mg[ww * 4 + 0]; qm1[t] = mg[ww * 4 + 1];
        ql0[t] = mg[ww * 4 + 2]; ql1[t] = mg[ww * 4 + 3];
    }
    float M0 = fmaxf(fmaxf(qm0[0], qm0[1]), fmaxf(qm0[2], qm0[3]));
    float M1 = fmaxf(fmaxf(qm1[0], qm1[1]), fmaxf(qm1[2], qm1[3]));
    float L0 = 0.f, L1 = 0.f;
    float sc0[4], sc1[4];
    #pragma unroll
    for (int t = 0; t < 4; ++t) {
        sc0[t] = __expf(qm0[t] - M0);  L0 = fmaf(ql0[t], sc0[t], L0);
        sc1[t] = __expf(qm1[t] - M1);  L1 = fmaf(ql1[t], sc1[t], L1);
    }
    const float invl0 = 1.0f / L0;
    const float invl1 = 1.0f / L1;

    // combined context store: quarter-0 warps only
    if (q == 0) {
        float4 C0 = make_float4(0.f,0.f,0.f,0.f);
        float4 C1 = C0;
        #pragma unroll
        for (int t = 0; t < 4; ++t) {
            int ww = j + t * NPAIR;
            float4 c0 = mgc[ww * 64 + lane];
            float4 c1 = mgc[ww * 64 + 32 + lane];
            C0.x = fmaf(c0.x, sc0[t], C0.x); C0.y = fmaf(c0.y, sc0[t], C0.y);
            C0.z = fmaf(c0.z, sc0[t], C0.z); C0.w = fmaf(c0.w, sc0[t], C0.w);
            C1.x = fmaf(c1.x, sc1[t], C1.x); C1.y = fmaf(c1.y, sc1[t], C1.y);
            C1.z = fmaf(c1.z, sc1[t], C1.z); C1.w = fmaf(c1.w, sc1[t], C1.w);
        }
        float4 co;
        co.x = C0.x * invl0; co.y = C0.y * invl0;
        co.z = C0.z * invl0; co.w = C0.w * invl0;
        ((float4*)c_out)[(b * TD + d0) * 32 + lane] = co;
        if (valid1) {
            co.x = C1.x * invl1; co.y = C1.y * invl1;
            co.z = C1.z * invl1; co.w = C1.w * invl1;
            ((float4*)c_out)[(b * TD + d1) * 32 + lane] = co;
        }
    }

    // attention weights: each warp writes its own 8 chunks with final (M, L)
    float* erow0 = e_out + (long)(b * TD + d0) * TE + q * (QCHUNK * TCHUNK);
    float* erow1 = e_out + (long)(b * TD + d1) * TE + q * (QCHUNK * TCHUNK);
    #pragma unroll 1
    for (int k = 0; k < QCHUNK; ++k) {
        erow0[k * TCHUNK + lane] = __expf(lgbuf0[k] - M0) * invl0;
        if (valid1)
            erow1[k * TCHUNK + lane] = __expf(lgbuf1[k] - M1) * invl1;
    }
}

// ---------------------------------------------------------------------------
extern "C" void kernel_launch(void* const* d_in, const int* in_sizes, int n_in,
                              void* d_out, int out_size)
{
    const float* enc = (const float*)d_in[0];   // [B, TE, H]
    const float* dec = (const float*)d_in[1];   // [B, TD, H]
    const float* W_a = (const float*)d_in[2];   // [H, H]
    const float* U_a = (const float*)d_in[3];   // [H, H]
    const float* V_a = (const float*)d_in[4];   // [H, 1]

    float* c_out = (float*)d_out;                        // [B, TD, H]
    float* e_out = (float*)d_out + (long)BB * TD * HH;   // [B, TD, TE]

    // Stage 1: both projections (192 CTAs x 8 warps x 4 rows = 6144 rows)
    proj_all_kernel<<<(BB * (TE + TD)) / 4 / 8, 256>>>(enc, dec, W_a, U_a);

    // Stage 2: fused attention (148 CTAs = 1 per SM, 28 warps, ~44 KB static)
    dim3 grid(NTILES, BB);
    attn_main_kernel<<<grid, NTHREADS>>>(enc, V_a, c_out, e_out);
}

// round 12
// speedup vs baseline: 1.3803x; 1.0225x over previous
#include <cuda_runtime.h>
#include <cuda_fp16.h>
#include <math_constants.h>

#define BB 4
#define TE 1024
#define TD 512
#define HH 128
#define DTILE 14        // d's per CTA: 7 pairs x (2 d's per warp)
#define NPAIR 7
#define NW 28           // warps per CTA: 7 pairs x 4 t-quarters
#define NTILES 37       // ceil(512/14); 4*37 = 148 CTAs = 1 per SM
#define TCHUNK 32
#define QCHUNK 8        // chunks per t-quarter
#define NTHREADS (NW * 32)          // 896

// Scratch (statically allocated; no cudaMalloc allowed anywhere)
// g_Ws_h: fp16, blocked-transposed. 16B slot S = ((b*32 + t/32)*16 + ho)*32
// + t%32 holds halves h = ho*8 .. ho*8+7 for that t. Phase-1 (lane = t)
// reads slot [ho][lane] -> coalesced LDG.128 carrying 8 h's.
__device__ __half g_Ws_h[BB * TE * HH];
__device__ float  g_Uh[BB * TD * HH];   // fp32 row layout: [row][h]

__device__ __forceinline__ __half2 htanh2(__half2 x) {
    unsigned xi = *reinterpret_cast<unsigned*>(&x);
    unsigned yi;
    asm("tanh.approx.f16x2 %0, %1;" : "=r"(yi) : "r"(xi));
    return *reinterpret_cast<__half2*>(&yi);
}
__device__ __forceinline__ unsigned pack2(float lo, float hi) {
    __half2 h = __floats2half2_rn(lo, hi);
    return *reinterpret_cast<unsigned*>(&h);
}

// ---------------------------------------------------------------------------
// Stage 1 (fused): rows 0..4095 -> g_Ws_h (fp16 blocked) = enc @ W_a;
// rows 4096..6143 -> g_Uh (fp32 rows) = dec @ U_a. 4 rows/warp.
// ---------------------------------------------------------------------------
__global__ __launch_bounds__(256) void proj_all_kernel(
    const float* __restrict__ enc, const float* __restrict__ dec,
    const float* __restrict__ Wa,  const float* __restrict__ Ua)
{
    const int w    = threadIdx.x >> 5;
    const int lane = threadIdx.x & 31;
    const int gw   = blockIdx.x * 8 + w;      // 0..1535
    int r0 = gw * 4;

    const bool isWs = (r0 < BB * TE);
    const float* in; const float* W;
    if (isWs) { in = enc; W = Wa; }
    else      { r0 -= BB * TE; in = dec; W = Ua; }

    const float4* in4 = (const float4*)in;
    const float4* W4  = (const float4*)W;

    float4 acc0 = make_float4(0.f,0.f,0.f,0.f);
    float4 acc1 = acc0, acc2 = acc0, acc3 = acc0;

    #pragma unroll 4
    for (int hg = 0; hg < HH / 4; ++hg) {
        float4 a0 = in4[(r0 + 0) * 32 + hg];
        float4 a1 = in4[(r0 + 1) * 32 + hg];
        float4 a2 = in4[(r0 + 2) * 32 + hg];
        float4 a3 = in4[(r0 + 3) * 32 + hg];
        #pragma unroll
        for (int j = 0; j < 4; ++j) {
            float4 wv = W4[(hg * 4 + j) * 32 + lane];
            float s0 = (j == 0) ? a0.x : (j == 1) ? a0.y : (j == 2) ? a0.z : a0.w;
            float s1 = (j == 0) ? a1.x : (j == 1) ? a1.y : (j == 2) ? a1.z : a1.w;
            float s2 = (j == 0) ? a2.x : (j == 1) ? a2.y : (j == 2) ? a2.z : a2.w;
            float s3 = (j == 0) ? a3.x : (j == 1) ? a3.y : (j == 2) ? a3.z : a3.w;
            acc0.x = fmaf(s0, wv.x, acc0.x); acc0.y = fmaf(s0, wv.y, acc0.y);
            acc0.z = fmaf(s0, wv.z, acc0.z); acc0.w = fmaf(s0, wv.w, acc0.w);
            acc1.x = fmaf(s1, wv.x, acc1.x); acc1.y = fmaf(s1, wv.y, acc1.y);
            acc1.z = fmaf(s1, wv.z, acc1.z); acc1.w = fmaf(s1, wv.w, acc1.w);
            acc2.x = fmaf(s2, wv.x, acc2.x); acc2.y = fmaf(s2, wv.y, acc2.y);
            acc2.z = fmaf(s2, wv.z, acc2.z); acc2.w = fmaf(s2, wv.w, acc2.w);
            acc3.x = fmaf(s3, wv.x, acc3.x); acc3.y = fmaf(s3, wv.y, acc3.y);
            acc3.z = fmaf(s3, wv.z, acc3.z); acc3.w = fmaf(s3, wv.w, acc3.w);
        }
    }
    if (isWs) {
        // fp16 blocked store: lane owns h = 4lane..4lane+3 -> oct lane>>1,
        // half-slot lane&1. 8-byte stores.
        uint2* W2 = (uint2*)g_Ws_h;
        const int bb    = r0 >> 10;
        const int t0    = r0 & 1023;
        const int chunk = t0 >> 5;
        const int tl    = t0 & 31;            // multiple of 4, +3 stays in chunk
        const int Sbase = ((bb * 32 + chunk) * 16 + (lane >> 1)) * 32;
        const int hs    = lane & 1;
        W2[(Sbase + tl + 0) * 2 + hs] = make_uint2(pack2(acc0.x, acc0.y), pack2(acc0.z, acc0.w));
        W2[(Sbase + tl + 1) * 2 + hs] = make_uint2(pack2(acc1.x, acc1.y), pack2(acc1.z, acc1.w));
        W2[(Sbase + tl + 2) * 2 + hs] = make_uint2(pack2(acc2.x, acc2.y), pack2(acc2.z, acc2.w));
        W2[(Sbase + tl + 3) * 2 + hs] = make_uint2(pack2(acc3.x, acc3.y), pack2(acc3.z, acc3.w));
    } else {
        float4* out4 = (float4*)g_Uh;
        out4[(r0 + 0) * 32 + lane] = acc0;
        out4[(r0 + 1) * 32 + lane] = acc1;
        out4[(r0 + 2) * 32 + lane] = acc2;
        out4[(r0 + 3) * 32 + lane] = acc3;
    }
}

// ---------------------------------------------------------------------------
// Stage 2: 28 warps = 7 d-pairs x 4 t-quarters; no staging, no loop barriers.
// Phase-1 is fp16: HADD2 + tanh.approx.f16x2 (2 tanh per MUFU op), fp32
// accumulate. Context & softmax stay fp32. 4-way flash merge at the end.
// ---------------------------------------------------------------------------
__global__ __launch_bounds__(NTHREADS, 1) void attn_main_kernel(
    const float* __restrict__ enc,   // [B, TE, H]
    const float* __restrict__ Va,    // [H]
    float* __restrict__ c_out,       // [B, TD, H]
    float* __restrict__ e_out)       // [B, TD, TE]
{
    __shared__ float4 uh_h[DTILE * 16];      // fp16 uh: 16 octs (8 halves) per d
    __shared__ float4 v_s [32];              // fp32 v
    __shared__ float  p_s [NW * 64];
    __shared__ float  mg  [NW * 4];          // m0, m1, l0, l1
    __shared__ float4 mgc [NW * 64];         // cacc0 | cacc1

    const int tid  = threadIdx.x;
    const int w    = tid >> 5;
    const int lane = tid & 31;
    const int q    = w / NPAIR;              // t-quarter 0..3
    const int j    = w % NPAIR;              // d-pair index 0..6
    const int b    = blockIdx.y;
    const int dbase = blockIdx.x * DTILE;
    const int d0   = dbase + j;              // max 510
    const int d1   = d0 + NPAIR;
    const bool valid1 = (d1 < TD);

    // one-time staging: uh rows 0..13 (fp32 -> fp16 octs) and v
    if (w < DTILE) {
        int dw = dbase + w;
        float4 u = make_float4(0.f,0.f,0.f,0.f);
        if (dw < TD) u = ((const float4*)g_Uh)[(b * TD + dw) * 32 + lane];
        uint2* uh2 = (uint2*)uh_h;
        uh2[(w * 16 + (lane >> 1)) * 2 + (lane & 1)] =
            make_uint2(pack2(u.x, u.y), pack2(u.z, u.w));
    }
    if (w == DTILE) v_s[lane] = ((const float4*)Va)[lane];
    __syncthreads();

    float m0 = -CUDART_INF_F, m1 = -CUDART_INF_F;
    float l0 = 0.f, l1 = 0.f;                // per-lane partials
    float4 cacc0 = make_float4(0.f,0.f,0.f,0.f);
    float4 cacc1 = cacc0;
    float lgbuf0[QCHUNK], lgbuf1[QCHUNK];

    const float4* wsblk  = (const float4*)g_Ws_h + (long)b * 32 * 16 * 32;
    const float4* esrc_b = (const float4*)(enc + (long)b * TE * HH);
    const float4* u0row  = uh_h + j * 16;
    const float4* u1row  = uh_h + (j + NPAIR) * 16;
    float* prow = p_s + w * 64;

    #pragma unroll 1
    for (int k = 0; k < QCHUNK; ++k) {
        const int chunk = q * QCHUNK + k;
        const float4* wschunk = wsblk + chunk * (16 * 32);

        // ---- Phase 1 (fp16): lane = t. Two logits per lane (d0, d1) ----
        float a0A = 0.f, a0B = 0.f, a1A = 0.f, a1B = 0.f;
        #pragma unroll 8
        for (int ho = 0; ho < 16; ++ho) {
            float4 wsq = wschunk[ho * 32 + lane];   // 8 halves, coalesced LDG.128
            float4 u0q = u0row[ho];                  // smem broadcast (8 halves)
            float4 u1q = u1row[ho];
            float4 va  = v_s[2 * ho];                // v fp32, h = ho*8..+3
            float4 vb  = v_s[2 * ho + 1];            //            h = ho*8+4..+7
            const __half2* wh  = (const __half2*)&wsq;
            const __half2* uh0 = (const __half2*)&u0q;
            const __half2* uh1 = (const __half2*)&u1q;
            const float vlo[4] = {va.x, va.z, vb.x, vb.z};
            const float vhi[4] = {va.y, va.w, vb.y, vb.w};
            #pragma unroll
            for (int p = 0; p < 4; ++p) {
                __half2 t0 = htanh2(__hadd2(wh[p], uh0[p]));
                __half2 t1 = htanh2(__hadd2(wh[p], uh1[p]));
                a0A = fmaf(vlo[p], __low2float(t0),  a0A);
                a0B = fmaf(vhi[p], __high2float(t0), a0B);
                a1A = fmaf(vlo[p], __low2float(t1),  a1A);
                a1B = fmaf(vhi[p], __high2float(t1), a1B);
            }
        }
        const float lgt0 = a0A + a0B;
        const float lgt1 = a1A + a1B;
        lgbuf0[k] = lgt0;
        lgbuf1[k] = lgt1;

        // ---- Online softmax (warp scope, both d's) ----
        float cm0 = lgt0, cm1 = lgt1;
        #pragma unroll
        for (int off = 16; off > 0; off >>= 1) {
            cm0 = fmaxf(cm0, __shfl_xor_sync(0xffffffffu, cm0, off));
            cm1 = fmaxf(cm1, __shfl_xor_sync(0xffffffffu, cm1, off));
        }
        if (cm0 > m0) {
            float corr = __expf(m0 - cm0);    // first iter: exp(-inf) = 0
            l0 *= corr;
            cacc0.x *= corr; cacc0.y *= corr; cacc0.z *= corr; cacc0.w *= corr;
            m0 = cm0;
        }
        if (cm1 > m1) {
            float corr = __expf(m1 - cm1);
            l1 *= corr;
            cacc1.x *= corr; cacc1.y *= corr; cacc1.z *= corr; cacc1.w *= corr;
            m1 = cm1;
        }
        float p0 = __expf(lgt0 - m0);
        float p1 = __expf(lgt1 - m1);
        l0 += p0; l1 += p1;
        prow[lane]      = p0;
        prow[32 + lane] = p1;
        __syncwarp();

        // ---- Context (fp32): lane = h-quad; enc via direct LDG ----
        const float4* encrow = esrc_b + chunk * (TCHUNK * 32);
        #pragma unroll 8
        for (int tt = 0; tt < TCHUNK; ++tt) {
            float pt0 = prow[tt];
            float pt1 = prow[32 + tt];
            float4 ev = encrow[tt * 32 + lane];
            cacc0.x = fmaf(pt0, ev.x, cacc0.x);
            cacc0.y = fmaf(pt0, ev.y, cacc0.y);
            cacc0.z = fmaf(pt0, ev.z, cacc0.z);
            cacc0.w = fmaf(pt0, ev.w, cacc0.w);
            cacc1.x = fmaf(pt1, ev.x, cacc1.x);
            cacc1.y = fmaf(pt1, ev.y, cacc1.y);
            cacc1.z = fmaf(pt1, ev.z, cacc1.z);
            cacc1.w = fmaf(pt1, ev.w, cacc1.w);
        }
        __syncwarp();   // prow consumed before next iteration overwrites
    }

    // reduce per-lane l partials within the warp
    #pragma unroll
    for (int off = 16; off > 0; off >>= 1) {
        l0 += __shfl_xor_sync(0xffffffffu, l0, off);
        l1 += __shfl_xor_sync(0xffffffffu, l1, off);
    }

    // ---- 4-way merge of (m, l, C) across quad {j, j+7, j+14, j+21} ----
    if (lane == 0) {
        mg[w * 4 + 0] = m0; mg[w * 4 + 1] = m1;
        mg[w * 4 + 2] = l0; mg[w * 4 + 3] = l1;
    }
    mgc[w * 64 + lane]      = cacc0;
    mgc[w * 64 + 32 + lane] = cacc1;
    __syncthreads();

    float qm0[4], qm1[4], ql0[4], ql1[4];
    #pragma unroll
    for (int t = 0; t < 4; ++t) {
        int ww = j + t * NPAIR;
        qm0[t] = mg[ww * 4 + 0]; qm1[t] = mg[ww * 4 + 1];
        ql0[t] = mg[ww * 4 + 2]; ql1[t] = mg[ww * 4 + 3];
    }
    float M0 = fmaxf(fmaxf(qm0[0], qm0[1]), fmaxf(qm0[2], qm0[3]));
    float M1 = fmaxf(fmaxf(qm1[0], qm1[1]), fmaxf(qm1[2], qm1[3]));
    float L0 = 0.f, L1 = 0.f;
    float sc0[4], sc1[4];
    #pragma unroll
    for (int t = 0; t < 4; ++t) {
        sc0[t] = __expf(qm0[t] - M0);  L0 = fmaf(ql0[t], sc0[t], L0);
        sc1[t] = __expf(qm1[t] - M1);  L1 = fmaf(ql1[t], sc1[t], L1);
    }
    const float invl0 = 1.0f / L0;
    const float invl1 = 1.0f / L1;

    // combined context store: quarter-0 warps only
    if (q == 0) {
        float4 C0 = make_float4(0.f,0.f,0.f,0.f);
        float4 C1 = C0;
        #pragma unroll
        for (int t = 0; t < 4; ++t) {
            int ww = j + t * NPAIR;
            float4 c0 = mgc[ww * 64 + lane];
            float4 c1 = mgc[ww * 64 + 32 + lane];
            C0.x = fmaf(c0.x, sc0[t], C0.x); C0.y = fmaf(c0.y, sc0[t], C0.y);
            C0.z = fmaf(c0.z, sc0[t], C0.z); C0.w = fmaf(c0.w, sc0[t], C0.w);
            C1.x = fmaf(c1.x, sc1[t], C1.x); C1.y = fmaf(c1.y, sc1[t], C1.y);
            C1.z = fmaf(c1.z, sc1[t], C1.z); C1.w = fmaf(c1.w, sc1[t], C1.w);
        }
        float4 co;
        co.x = C0.x * invl0; co.y = C0.y * invl0;
        co.z = C0.z * invl0; co.w = C0.w * invl0;
        ((float4*)c_out)[(b * TD + d0) * 32 + lane] = co;
        if (valid1) {
            co.x = C1.x * invl1; co.y = C1.y * invl1;
            co.z = C1.z * invl1; co.w = C1.w * invl1;
            ((float4*)c_out)[(b * TD + d1) * 32 + lane] = co;
        }
    }

    // attention weights: each warp writes its own 8 chunks with final (M, L)
    float* erow0 = e_out + (long)(b * TD + d0) * TE + q * (QCHUNK * TCHUNK);
    float* erow1 = e_out + (long)(b * TD + d1) * TE + q * (QCHUNK * TCHUNK);
    #pragma unroll 1
    for (int k = 0; k < QCHUNK; ++k) {
        erow0[k * TCHUNK + lane] = __expf(lgbuf0[k] - M0) * invl0;
        if (valid1)
            erow1[k * TCHUNK + lane] = __expf(lgbuf1[k] - M1) * invl1;
    }
}

// ---------------------------------------------------------------------------
extern "C" void kernel_launch(void* const* d_in, const int* in_sizes, int n_in,
                              void* d_out, int out_size)
{
    const float* enc = (const float*)d_in[0];   // [B, TE, H]
    const float* dec = (const float*)d_in[1];   // [B, TD, H]
    const float* W_a = (const float*)d_in[2];   // [H, H]
    const float* U_a = (const float*)d_in[3];   // [H, H]
    const float* V_a = (const float*)d_in[4];   // [H, 1]

    float* c_out = (float*)d_out;                        // [B, TD, H]
    float* e_out = (float*)d_out + (long)BB * TD * HH;   // [B, TD, TE]

    // Stage 1: both projections (192 CTAs x 8 warps x 4 rows = 6144 rows)
    proj_all_kernel<<<(BB * (TE + TD)) / 4 / 8, 256>>>(enc, dec, W_a, U_a);

    // Stage 2: fused attention (148 CTAs = 1 per SM, 28 warps)
    dim3 grid(NTILES, BB);
    attn_main_kernel<<<grid, NTHREADS>>>(enc, V_a, c_out, e_out);
}

// round 14
// speedup vs baseline: 1.4502x; 1.0507x over previous
#include <cuda_runtime.h>
#include <cuda_fp16.h>
#include <math_constants.h>

#define BB 4
#define TE 1024
#define TD 512
#define HH 128
#define DTILE 14        // d's per CTA: 7 pairs x (2 d's per warp)
#define NPAIR 7
#define NW 28           // warps per CTA: 7 pairs x 4 t-quarters
#define NTILES 37       // ceil(512/14); 4*37 = 148 CTAs = 1 per SM
#define TCHUNK 32
#define QCHUNK 8        // chunks per t-quarter
#define NTHREADS (NW * 32)          // 896

// Scratch (statically allocated; no cudaMalloc allowed anywhere)
// g_Ws_h: fp16, blocked-transposed. 16B slot S = ((b*32 + t/32)*16 + ho)*32
// + t%32 holds halves h = ho*8 .. ho*8+7 for that t. Phase-1 (lane = t)
// reads slot [ho][lane] -> coalesced LDG.128 carrying 8 h's.
__device__ __half g_Ws_h[BB * TE * HH];
__device__ float  g_Uh[BB * TD * HH];   // fp32 row layout: [row][h]

__device__ __forceinline__ __half2 htanh2(__half2 x) {
    unsigned xi = *reinterpret_cast<unsigned*>(&x);
    unsigned yi;
    asm("tanh.approx.f16x2 %0, %1;" : "=r"(yi) : "r"(xi));
    return *reinterpret_cast<__half2*>(&yi);
}
__device__ __forceinline__ unsigned pack2(float lo, float hi) {
    __half2 h = __floats2half2_rn(lo, hi);
    return *reinterpret_cast<unsigned*>(&h);
}

// ---------------------------------------------------------------------------
// Stage 1 (fused): rows 0..4095 -> g_Ws_h (fp16 blocked) = enc @ W_a;
// rows 4096..6143 -> g_Uh (fp32 rows) = dec @ U_a. 4 rows/warp.
// ---------------------------------------------------------------------------
__global__ __launch_bounds__(256) void proj_all_kernel(
    const float* __restrict__ enc, const float* __restrict__ dec,
    const float* __restrict__ Wa,  const float* __restrict__ Ua)
{
    const int w    = threadIdx.x >> 5;
    const int lane = threadIdx.x & 31;
    const int gw   = blockIdx.x * 8 + w;      // 0..1535
    int r0 = gw * 4;

    const bool isWs = (r0 < BB * TE);
    const float* in; const float* W;
    if (isWs) { in = enc; W = Wa; }
    else      { r0 -= BB * TE; in = dec; W = Ua; }

    const float4* in4 = (const float4*)in;
    const float4* W4  = (const float4*)W;

    float4 acc0 = make_float4(0.f,0.f,0.f,0.f);
    float4 acc1 = acc0, acc2 = acc0, acc3 = acc0;

    #pragma unroll 4
    for (int hg = 0; hg < HH / 4; ++hg) {
        float4 a0 = in4[(r0 + 0) * 32 + hg];
        float4 a1 = in4[(r0 + 1) * 32 + hg];
        float4 a2 = in4[(r0 + 2) * 32 + hg];
        float4 a3 = in4[(r0 + 3) * 32 + hg];
        #pragma unroll
        for (int j = 0; j < 4; ++j) {
            float4 wv = W4[(hg * 4 + j) * 32 + lane];
            float s0 = (j == 0) ? a0.x : (j == 1) ? a0.y : (j == 2) ? a0.z : a0.w;
            float s1 = (j == 0) ? a1.x : (j == 1) ? a1.y : (j == 2) ? a1.z : a1.w;
            float s2 = (j == 0) ? a2.x : (j == 1) ? a2.y : (j == 2) ? a2.z : a2.w;
            float s3 = (j == 0) ? a3.x : (j == 1) ? a3.y : (j == 2) ? a3.z : a3.w;
            acc0.x = fmaf(s0, wv.x, acc0.x); acc0.y = fmaf(s0, wv.y, acc0.y);
            acc0.z = fmaf(s0, wv.z, acc0.z); acc0.w = fmaf(s0, wv.w, acc0.w);
            acc1.x = fmaf(s1, wv.x, acc1.x); acc1.y = fmaf(s1, wv.y, acc1.y);
            acc1.z = fmaf(s1, wv.z, acc1.z); acc1.w = fmaf(s1, wv.w, acc1.w);
            acc2.x = fmaf(s2, wv.x, acc2.x); acc2.y = fmaf(s2, wv.y, acc2.y);
            acc2.z = fmaf(s2, wv.z, acc2.z); acc2.w = fmaf(s2, wv.w, acc2.w);
            acc3.x = fmaf(s3, wv.x, acc3.x); acc3.y = fmaf(s3, wv.y, acc3.y);
            acc3.z = fmaf(s3, wv.z, acc3.z); acc3.w = fmaf(s3, wv.w, acc3.w);
        }
    }
    if (isWs) {
        // fp16 blocked store: lane owns h = 4lane..4lane+3 -> oct lane>>1,
        // half-slot lane&1. 8-byte stores.
        uint2* W2 = (uint2*)g_Ws_h;
        const int bb    = r0 >> 10;
        const int t0    = r0 & 1023;
        const int chunk = t0 >> 5;
        const int tl    = t0 & 31;            // multiple of 4, +3 stays in chunk
        const int Sbase = ((bb * 32 + chunk) * 16 + (lane >> 1)) * 32;
        const int hs    = lane & 1;
        W2[(Sbase + tl + 0) * 2 + hs] = make_uint2(pack2(acc0.x, acc0.y), pack2(acc0.z, acc0.w));
        W2[(Sbase + tl + 1) * 2 + hs] = make_uint2(pack2(acc1.x, acc1.y), pack2(acc1.z, acc1.w));
        W2[(Sbase + tl + 2) * 2 + hs] = make_uint2(pack2(acc2.x, acc2.y), pack2(acc2.z, acc2.w));
        W2[(Sbase + tl + 3) * 2 + hs] = make_uint2(pack2(acc3.x, acc3.y), pack2(acc3.z, acc3.w));
    } else {
        float4* out4 = (float4*)g_Uh;
        out4[(r0 + 0) * 32 + lane] = acc0;
        out4[(r0 + 1) * 32 + lane] = acc1;
        out4[(r0 + 2) * 32 + lane] = acc2;
        out4[(r0 + 3) * 32 + lane] = acc3;
    }
}

// ---------------------------------------------------------------------------
// Stage 2: 28 warps = 7 d-pairs x 4 t-quarters; no staging, no loop barriers.
// Phase-1 fully fp16: HADD2 + tanh.approx.f16x2 + HFMA2 accumulate (v in
// fp16) — zero per-element conversions. Per-chunk epilogue converts the 8
// half2 partials to fp32. Softmax/context stay fp32. 4-way flash merge.
// ---------------------------------------------------------------------------
__global__ __launch_bounds__(NTHREADS, 1) void attn_main_kernel(
    const float* __restrict__ enc,   // [B, TE, H]
    const float* __restrict__ Va,    // [H]
    float* __restrict__ c_out,       // [B, TD, H]
    float* __restrict__ e_out)       // [B, TD, TE]
{
    __shared__ float4 uh_h[DTILE * 16];      // fp16 uh: 16 octs (8 halves) per d
    __shared__ float4 vh_s[16];              // fp16 v: oct ho = 8 halves
    __shared__ float  p_s [NW * 64];
    __shared__ float  mg  [NW * 4];          // m0, m1, l0, l1
    __shared__ float4 mgc [NW * 64];         // cacc0 | cacc1

    const int tid  = threadIdx.x;
    const int w    = tid >> 5;
    const int lane = tid & 31;
    const int q    = w / NPAIR;              // t-quarter 0..3
    const int j    = w % NPAIR;              // d-pair index 0..6
    const int b    = blockIdx.y;
    const int dbase = blockIdx.x * DTILE;
    const int d0   = dbase + j;              // max 510
    const int d1   = d0 + NPAIR;
    const bool valid1 = (d1 < TD);

    // one-time staging: uh rows 0..13 (fp32 -> fp16 octs) and v (fp16 octs)
    if (w < DTILE) {
        int dw = dbase + w;
        float4 u = make_float4(0.f,0.f,0.f,0.f);
        if (dw < TD) u = ((const float4*)g_Uh)[(b * TD + dw) * 32 + lane];
        uint2* uh2 = (uint2*)uh_h;
        uh2[(w * 16 + (lane >> 1)) * 2 + (lane & 1)] =
            make_uint2(pack2(u.x, u.y), pack2(u.z, u.w));
    }
    if (w == DTILE && lane < 16) {
        float4 va = ((const float4*)Va)[2 * lane];
        float4 vb = ((const float4*)Va)[2 * lane + 1];
        uint4 pk;
        pk.x = pack2(va.x, va.y); pk.y = pack2(va.z, va.w);
        pk.z = pack2(vb.x, vb.y); pk.w = pack2(vb.z, vb.w);
        ((uint4*)vh_s)[lane] = pk;
    }
    __syncthreads();

    float m0 = -CUDART_INF_F, m1 = -CUDART_INF_F;
    float l0 = 0.f, l1 = 0.f;                // per-lane partials
    float4 cacc0 = make_float4(0.f,0.f,0.f,0.f);
    float4 cacc1 = cacc0;
    float lgbuf0[QCHUNK], lgbuf1[QCHUNK];

    const float4* wsblk  = (const float4*)g_Ws_h + (long)b * 32 * 16 * 32;
    const float4* esrc_b = (const float4*)(enc + (long)b * TE * HH);
    const float4* u0row  = uh_h + j * 16;
    const float4* u1row  = uh_h + (j + NPAIR) * 16;
    float* prow = p_s + w * 64;

    const __half2 hzero = __float2half2_rn(0.f);

    #pragma unroll 1
    for (int k = 0; k < QCHUNK; ++k) {
        const int chunk = q * QCHUNK + k;
        const float4* wschunk = wsblk + chunk * (16 * 32);

        // ---- Phase 1 (all-fp16): lane = t. Two logits per lane ----
        __half2 a0h0 = hzero, a0h1 = hzero, a0h2 = hzero, a0h3 = hzero;
        __half2 a1h0 = hzero, a1h1 = hzero, a1h2 = hzero, a1h3 = hzero;
        #pragma unroll 8
        for (int ho = 0; ho < 16; ++ho) {
            float4 wsq = wschunk[ho * 32 + lane];   // 8 halves, coalesced LDG.128
            float4 u0q = u0row[ho];                  // smem broadcast (8 halves)
            float4 u1q = u1row[ho];
            float4 vq  = vh_s[ho];                   // fp16 v oct
            const __half2* wh = (const __half2*)&wsq;
            const __half2* u0 = (const __half2*)&u0q;
            const __half2* u1 = (const __half2*)&u1q;
            const __half2* vv = (const __half2*)&vq;
            a0h0 = __hfma2(vv[0], htanh2(__hadd2(wh[0], u0[0])), a0h0);
            a1h0 = __hfma2(vv[0], htanh2(__hadd2(wh[0], u1[0])), a1h0);
            a0h1 = __hfma2(vv[1], htanh2(__hadd2(wh[1], u0[1])), a0h1);
            a1h1 = __hfma2(vv[1], htanh2(__hadd2(wh[1], u1[1])), a1h1);
            a0h2 = __hfma2(vv[2], htanh2(__hadd2(wh[2], u0[2])), a0h2);
            a1h2 = __hfma2(vv[2], htanh2(__hadd2(wh[2], u1[2])), a1h2);
            a0h3 = __hfma2(vv[3], htanh2(__hadd2(wh[3], u0[3])), a0h3);
            a1h3 = __hfma2(vv[3], htanh2(__hadd2(wh[3], u1[3])), a1h3);
        }
        // epilogue: convert 4 half2 partials per d to fp32 and sum
        float2 f00 = __half22float2(a0h0), f01 = __half22float2(a0h1);
        float2 f02 = __half22float2(a0h2), f03 = __half22float2(a0h3);
        float2 f10 = __half22float2(a1h0), f11 = __half22float2(a1h1);
        float2 f12 = __half22float2(a1h2), f13 = __half22float2(a1h3);
        const float lgt0 = ((f00.x + f00.y) + (f01.x + f01.y))
                         + ((f02.x + f02.y) + (f03.x + f03.y));
        const float lgt1 = ((f10.x + f10.y) + (f11.x + f11.y))
                         + ((f12.x + f12.y) + (f13.x + f13.y));
        lgbuf0[k] = lgt0;
        lgbuf1[k] = lgt1;

        // ---- Online softmax (warp scope, both d's) ----
        float cm0 = lgt0, cm1 = lgt1;
        #pragma unroll
        for (int off = 16; off > 0; off >>= 1) {
            cm0 = fmaxf(cm0, __shfl_xor_sync(0xffffffffu, cm0, off));
            cm1 = fmaxf(cm1, __shfl_xor_sync(0xffffffffu, cm1, off));
        }
        if (cm0 > m0) {
            float corr = __expf(m0 - cm0);    // first iter: exp(-inf) = 0
            l0 *= corr;
            cacc0.x *= corr; cacc0.y *= corr; cacc0.z *= corr; cacc0.w *= corr;
            m0 = cm0;
        }
        if (cm1 > m1) {
            float corr = __expf(m1 - cm1);
            l1 *= corr;
            cacc1.x *= corr; cacc1.y *= corr; cacc1.z *= corr; cacc1.w *= corr;
            m1 = cm1;
        }
        float p0 = __expf(lgt0 - m0);
        float p1 = __expf(lgt1 - m1);
        l0 += p0; l1 += p1;
        prow[lane]      = p0;
        prow[32 + lane] = p1;
        __syncwarp();

        // ---- Context (fp32): lane = h-quad; enc via direct LDG ----
        const float4* encrow = esrc_b + chunk * (TCHUNK * 32);
        #pragma unroll 8
        for (int tt = 0; tt < TCHUNK; ++tt) {
            float pt0 = prow[tt];
            float pt1 = prow[32 + tt];
            float4 ev = encrow[tt * 32 + lane];
            cacc0.x = fmaf(pt0, ev.x, cacc0.x);
            cacc0.y = fmaf(pt0, ev.y, cacc0.y);
            cacc0.z = fmaf(pt0, ev.z, cacc0.z);
            cacc0.w = fmaf(pt0, ev.w, cacc0.w);
            cacc1.x = fmaf(pt1, ev.x, cacc1.x);
            cacc1.y = fmaf(pt1, ev.y, cacc1.y);
            cacc1.z = fmaf(pt1, ev.z, cacc1.z);
            cacc1.w = fmaf(pt1, ev.w, cacc1.w);
        }
        __syncwarp();   // prow consumed before next iteration overwrites
    }

    // reduce per-lane l partials within the warp
    #pragma unroll
    for (int off = 16; off > 0; off >>= 1) {
        l0 += __shfl_xor_sync(0xffffffffu, l0, off);
        l1 += __shfl_xor_sync(0xffffffffu, l1, off);
    }

    // ---- 4-way merge of (m, l, C) across quad {j, j+7, j+14, j+21} ----
    if (lane == 0) {
        mg[w * 4 + 0] = m0; mg[w * 4 + 1] = m1;
        mg[w * 4 + 2] = l0; mg[w * 4 + 3] = l1;
    }
    mgc[w * 64 + lane]      = cacc0;
    mgc[w * 64 + 32 + lane] = cacc1;
    __syncthreads();

    float qm0[4], qm1[4], ql0[4], ql1[4];
    #pragma unroll
    for (int t = 0; t < 4; ++t) {
        int ww = j + t * NPAIR;
        qm0[t] = mg[ww * 4 + 0]; qm1[t] = mg[ww * 4 + 1];
        ql0[t] = mg[ww * 4 + 2]; ql1[t] = mg[ww * 4 + 3];
    }
    float M0 = fmaxf(fmaxf(qm0[0], qm0[1]), fmaxf(qm0[2], qm0[3]));
    float M1 = fmaxf(fmaxf(qm1[0], qm1[1]), fmaxf(qm1[2], qm1[3]));
    float L0 = 0.f, L1 = 0.f;
    float sc0[4], sc1[4];
    #pragma unroll
    for (int t = 0; t < 4; ++t) {
        sc0[t] = __expf(qm0[t] - M0);  L0 = fmaf(ql0[t], sc0[t], L0);
        sc1[t] = __expf(qm1[t] - M1);  L1 = fmaf(ql1[t], sc1[t], L1);
    }
    const float invl0 = 1.0f / L0;
    const float invl1 = 1.0f / L1;

    // combined context store: quarter-0 warps only
    if (q == 0) {
        float4 C0 = make_float4(0.f,0.f,0.f,0.f);
        float4 C1 = C0;
        #pragma unroll
        for (int t = 0; t < 4; ++t) {
            int ww = j + t * NPAIR;
            float4 c0 = mgc[ww * 64 + lane];
            float4 c1 = mgc[ww * 64 + 32 + lane];
            C0.x = fmaf(c0.x, sc0[t], C0.x); C0.y = fmaf(c0.y, sc0[t], C0.y);
            C0.z = fmaf(c0.z, sc0[t], C0.z); C0.w = fmaf(c0.w, sc0[t], C0.w);
            C1.x = fmaf(c1.x, sc1[t], C1.x); C1.y = fmaf(c1.y, sc1[t], C1.y);
            C1.z = fmaf(c1.z, sc1[t], C1.z); C1.w = fmaf(c1.w, sc1[t], C1.w);
        }
        float4 co;
        co.x = C0.x * invl0; co.y = C0.y * invl0;
        co.z = C0.z * invl0; co.w = C0.w * invl0;
        ((float4*)c_out)[(b * TD + d0) * 32 + lane] = co;
        if (valid1) {
            co.x = C1.x * invl1; co.y = C1.y * invl1;
            co.z = C1.z * invl1; co.w = C1.w * invl1;
            ((float4*)c_out)[(b * TD + d1) * 32 + lane] = co;
        }
    }

    // attention weights: each warp writes its own 8 chunks with final (M, L)
    float* erow0 = e_out + (long)(b * TD + d0) * TE + q * (QCHUNK * TCHUNK);
    float* erow1 = e_out + (long)(b * TD + d1) * TE + q * (QCHUNK * TCHUNK);
    #pragma unroll 1
    for (int k = 0; k < QCHUNK; ++k) {
        erow0[k * TCHUNK + lane] = __expf(lgbuf0[k] - M0) * invl0;
        if (valid1)
            erow1[k * TCHUNK + lane] = __expf(lgbuf1[k] - M1) * invl1;
    }
}

// ---------------------------------------------------------------------------
extern "C" void kernel_launch(void* const* d_in, const int* in_sizes, int n_in,
                              void* d_out, int out_size)
{
    const float* enc = (const float*)d_in[0];   // [B, TE, H]
    const float* dec = (const float*)d_in[1];   // [B, TD, H]
    const float* W_a = (const float*)d_in[2];   // [H, H]
    const float* U_a = (const float*)d_in[3];   // [H, H]
    const float* V_a = (const float*)d_in[4];   // [H, 1]

    float* c_out = (float*)d_out;                        // [B, TD, H]
    float* e_out = (float*)d_out + (long)BB * TD * HH;   // [B, TD, TE]

    // Stage 1: both projections (192 CTAs x 8 warps x 4 rows = 6144 rows)
    proj_all_kernel<<<(BB * (TE + TD)) / 4 / 8, 256>>>(enc, dec, W_a, U_a);

    // Stage 2: fused attention (148 CTAs = 1 per SM, 28 warps)
    dim3 grid(NTILES, BB);
    attn_main_kernel<<<grid, NTHREADS>>>(enc, V_a, c_out, e_out);
}